// round 2
// baseline (speedup 1.0000x reference)
#include <cuda_runtime.h>
#include <cstdint>
#include <cstddef>

#define TTOK 2048
#define DDIM 2048
#define FDIM 4096
#define NEXP 8
#define NPOS (TTOK * 2)

// ---------------- scratch (static device globals; no allocation) ----------------
__device__ int   g_counts[NEXP];
__device__ int   g_offsets[NEXP + 1];
__device__ int   g_fill[NEXP];
__device__ int   g_topk_idx[NPOS];
__device__ float g_topk_w[NPOS];
__device__ int   g_row_token[NPOS];   // packed row -> token
__device__ float g_row_w[NPOS];       // packed row -> routing weight
__device__ int   g_token_pos[NPOS];   // (t,k) -> packed row
__device__ float g_act[(size_t)NPOS * FDIM];  // 64 MB: gelu(gate)*up, packed rows
__device__ float g_y[(size_t)NPOS * DDIM];    // 32 MB: scaled down-proj, packed rows

// ---------------- helpers ----------------
__device__ __forceinline__ uint32_t f2tf(float x) {
    uint32_t r;
    asm("cvt.rna.tf32.f32 %0, %1;" : "=r"(r) : "f"(x));
    return r;
}

__device__ __forceinline__ void mma8(float* c, const uint32_t* a, const uint32_t* b) {
    asm volatile(
        "mma.sync.aligned.m16n8k8.row.col.f32.tf32.tf32.f32 "
        "{%0,%1,%2,%3},{%4,%5,%6,%7},{%8,%9},{%0,%1,%2,%3};\n"
        : "+f"(c[0]), "+f"(c[1]), "+f"(c[2]), "+f"(c[3])
        : "r"(a[0]), "r"(a[1]), "r"(a[2]), "r"(a[3]), "r"(b[0]), "r"(b[1]));
}

__device__ __forceinline__ float gelu_tanh(float x) {
    float x3 = x * x * x;
    return 0.5f * x * (1.0f + tanhf(0.7978845608028654f * (x + 0.044715f * x3)));
}

// ---------------- router ----------------
__global__ void k_reset() {
    if (threadIdx.x < NEXP) g_counts[threadIdx.x] = 0;
}

__global__ void k_router(const float* __restrict__ hs, const float* __restrict__ gw) {
    const int warp = threadIdx.x >> 5;
    const int lane = threadIdx.x & 31;
    const int t = blockIdx.x * 8 + warp;
    if (t >= TTOK) return;

    float acc[NEXP];
#pragma unroll
    for (int e = 0; e < NEXP; e++) acc[e] = 0.0f;

    const float* hrow = hs + (size_t)t * DDIM;
    for (int d = lane; d < DDIM; d += 32) {
        float x = hrow[d];
        const float* g = gw + d * NEXP;
#pragma unroll
        for (int e = 0; e < NEXP; e++) acc[e] = fmaf(x, g[e], acc[e]);
    }
#pragma unroll
    for (int e = 0; e < NEXP; e++) {
#pragma unroll
        for (int o = 16; o > 0; o >>= 1) acc[e] += __shfl_xor_sync(0xffffffffu, acc[e], o);
    }

    if (lane == 0) {
        float l[NEXP];
#pragma unroll
        for (int e = 0; e < NEXP; e++) l[e] = tanhf(acc[e] / 30.0f) * 30.0f;
        // top-2, first-occurrence tie-breaking (matches jax.lax.top_k)
        int i0 = 0;
#pragma unroll
        for (int e = 1; e < NEXP; e++) if (l[e] > l[i0]) i0 = e;
        int i1 = -1;
#pragma unroll
        for (int e = 0; e < NEXP; e++) {
            if (e == i0) continue;
            if (i1 < 0 || l[e] > l[i1]) i1 = e;
        }
        float ee = expf(l[i1] - l[i0]);
        float w0 = 1.0f / (1.0f + ee);
        float w1 = ee / (1.0f + ee);
        g_topk_idx[t * 2 + 0] = i0;
        g_topk_idx[t * 2 + 1] = i1;
        g_topk_w[t * 2 + 0] = w0;
        g_topk_w[t * 2 + 1] = w1;
        atomicAdd(&g_counts[i0], 1);
        atomicAdd(&g_counts[i1], 1);
    }
}

__global__ void k_scan() {
    if (threadIdx.x == 0) {
        int o = 0;
#pragma unroll
        for (int e = 0; e < NEXP; e++) {
            g_offsets[e] = o;
            g_fill[e] = o;
            o += g_counts[e];
        }
        g_offsets[NEXP] = o;
    }
}

__global__ void k_assign() {
    const int t = blockIdx.x * blockDim.x + threadIdx.x;
    if (t >= TTOK) return;
#pragma unroll
    for (int k = 0; k < 2; k++) {
        int e = g_topk_idx[t * 2 + k];
        int pos = atomicAdd(&g_fill[e], 1);
        g_row_token[pos] = t;
        g_row_w[pos] = g_topk_w[t * 2 + k];
        g_token_pos[t * 2 + k] = pos;
    }
}

// ---------------- mlp1: act = gelu(X@Wg) * (X@Wu), per expert, gathered rows --------
// Block tile: 128(M) x 64(N) x 32(K), 8 warps (4x2), warp tile 32x32, tf32 mma m16n8k8.
__global__ void __launch_bounds__(256) k_mlp1(const float* __restrict__ hs,
                                              const float* __restrict__ wg,
                                              const float* __restrict__ wu) {
    extern __shared__ uint32_t smem[];
    const int e = blockIdx.z;
    const int seg_beg = g_offsets[e];
    const int seg_end = g_offsets[e + 1];
    const int seg_len = seg_end - seg_beg;
    if ((int)blockIdx.y * 128 >= seg_len) return;
    const int pos_base = seg_beg + blockIdx.y * 128;
    const int n0 = blockIdx.x * 64;

    uint32_t* sA  = smem;           // 2 buffers * 128*36
    uint32_t* sBg = smem + 9216;    // 2 buffers * 32*72
    uint32_t* sBu = smem + 13824;   // 2 buffers * 32*72

    const int tid = threadIdx.x;
    const int lane = tid & 31;
    const int warp = tid >> 5;
    const int wm = warp & 3;
    const int wn = warp >> 2;
    const int lr = lane >> 2;
    const int lc = lane & 3;

    // A gather coordinates: 2 threads/row, 16 floats each
    const int ar = tid >> 1;
    const int aj = (tid & 1) * 16;
    int apos = pos_base + ar;
    if (apos >= seg_end) apos = seg_end - 1;  // clamp; epilogue guards stores
    const float* aptr = hs + (size_t)g_row_token[apos] * DDIM + aj;

    // B coordinates: 16 threads per k-row, float4 each; covers k rows {bk, bk+16}
    const int bk = tid >> 4;
    const int bf = (tid & 15) * 4;
    const float* bgp = wg + (size_t)e * DDIM * FDIM + (size_t)bk * FDIM + n0 + bf;
    const float* bup = wu + (size_t)e * DDIM * FDIM + (size_t)bk * FDIM + n0 + bf;

    float accg[2][4][4], accu[2][4][4];
#pragma unroll
    for (int m = 0; m < 2; m++)
#pragma unroll
        for (int n = 0; n < 4; n++)
#pragma unroll
            for (int i = 0; i < 4; i++) { accg[m][n][i] = 0.0f; accu[m][n][i] = 0.0f; }

    float4 ra[4], rg[2], ru[2];

    // prefetch k-tile 0 (global -> regs)
#pragma unroll
    for (int i = 0; i < 4; i++) ra[i] = *(const float4*)(aptr + i * 4);
    rg[0] = *(const float4*)(bgp);
    rg[1] = *(const float4*)(bgp + (size_t)16 * FDIM);
    ru[0] = *(const float4*)(bup);
    ru[1] = *(const float4*)(bup + (size_t)16 * FDIM);

    // store tile 0 into buffer 0
    {
        uint32_t* A = sA;
#pragma unroll
        for (int i = 0; i < 4; i++) {
            A[ar * 36 + aj + i * 4 + 0] = f2tf(ra[i].x);
            A[ar * 36 + aj + i * 4 + 1] = f2tf(ra[i].y);
            A[ar * 36 + aj + i * 4 + 2] = f2tf(ra[i].z);
            A[ar * 36 + aj + i * 4 + 3] = f2tf(ra[i].w);
        }
        uint4 v;
        v.x = f2tf(rg[0].x); v.y = f2tf(rg[0].y); v.z = f2tf(rg[0].z); v.w = f2tf(rg[0].w);
        *(uint4*)(sBg + bk * 72 + bf) = v;
        v.x = f2tf(rg[1].x); v.y = f2tf(rg[1].y); v.z = f2tf(rg[1].z); v.w = f2tf(rg[1].w);
        *(uint4*)(sBg + (bk + 16) * 72 + bf) = v;
        v.x = f2tf(ru[0].x); v.y = f2tf(ru[0].y); v.z = f2tf(ru[0].z); v.w = f2tf(ru[0].w);
        *(uint4*)(sBu + bk * 72 + bf) = v;
        v.x = f2tf(ru[1].x); v.y = f2tf(ru[1].y); v.z = f2tf(ru[1].z); v.w = f2tf(ru[1].w);
        *(uint4*)(sBu + (bk + 16) * 72 + bf) = v;
    }
    __syncthreads();

    const int KT = DDIM / 32;  // 64
    for (int kt = 0; kt < KT; ++kt) {
        const int buf = kt & 1;
        if (kt + 1 < KT) {
            const int k0 = (kt + 1) * 32;
#pragma unroll
            for (int i = 0; i < 4; i++) ra[i] = *(const float4*)(aptr + k0 + i * 4);
            rg[0] = *(const float4*)(bgp + (size_t)k0 * FDIM);
            rg[1] = *(const float4*)(bgp + (size_t)(k0 + 16) * FDIM);
            ru[0] = *(const float4*)(bup + (size_t)k0 * FDIM);
            ru[1] = *(const float4*)(bup + (size_t)(k0 + 16) * FDIM);
        }
        // compute on current buffer
        const uint32_t* A  = sA + buf * 4608;
        const uint32_t* Bg = sBg + buf * 2304;
        const uint32_t* Bu = sBu + buf * 2304;
#pragma unroll
        for (int ks = 0; ks < 4; ++ks) {
            const int k = ks * 8;
            uint32_t a[2][4];
#pragma unroll
            for (int m = 0; m < 2; m++) {
                const int r0 = wm * 32 + m * 16;
                a[m][0] = A[(r0 + lr) * 36 + k + lc];
                a[m][1] = A[(r0 + 8 + lr) * 36 + k + lc];
                a[m][2] = A[(r0 + lr) * 36 + k + 4 + lc];
                a[m][3] = A[(r0 + 8 + lr) * 36 + k + 4 + lc];
            }
#pragma unroll
            for (int n = 0; n < 4; n++) {
                const int c0 = wn * 32 + n * 8 + lr;
                uint32_t bg2[2], bu2[2];
                bg2[0] = Bg[(k + lc) * 72 + c0];
                bg2[1] = Bg[(k + 4 + lc) * 72 + c0];
                bu2[0] = Bu[(k + lc) * 72 + c0];
                bu2[1] = Bu[(k + 4 + lc) * 72 + c0];
#pragma unroll
                for (int m = 0; m < 2; m++) {
                    mma8(accg[m][n], a[m], bg2);
                    mma8(accu[m][n], a[m], bu2);
                }
            }
        }
        // store prefetched tile into other buffer
        if (kt + 1 < KT) {
            const int nb = buf ^ 1;
            uint32_t* A2  = sA + nb * 4608;
            uint32_t* Bg2 = sBg + nb * 2304;
            uint32_t* Bu2 = sBu + nb * 2304;
#pragma unroll
            for (int i = 0; i < 4; i++) {
                A2[ar * 36 + aj + i * 4 + 0] = f2tf(ra[i].x);
                A2[ar * 36 + aj + i * 4 + 1] = f2tf(ra[i].y);
                A2[ar * 36 + aj + i * 4 + 2] = f2tf(ra[i].z);
                A2[ar * 36 + aj + i * 4 + 3] = f2tf(ra[i].w);
            }
            uint4 v;
            v.x = f2tf(rg[0].x); v.y = f2tf(rg[0].y); v.z = f2tf(rg[0].z); v.w = f2tf(rg[0].w);
            *(uint4*)(Bg2 + bk * 72 + bf) = v;
            v.x = f2tf(rg[1].x); v.y = f2tf(rg[1].y); v.z = f2tf(rg[1].z); v.w = f2tf(rg[1].w);
            *(uint4*)(Bg2 + (bk + 16) * 72 + bf) = v;
            v.x = f2tf(ru[0].x); v.y = f2tf(ru[0].y); v.z = f2tf(ru[0].z); v.w = f2tf(ru[0].w);
            *(uint4*)(Bu2 + bk * 72 + bf) = v;
            v.x = f2tf(ru[1].x); v.y = f2tf(ru[1].y); v.z = f2tf(ru[1].z); v.w = f2tf(ru[1].w);
            *(uint4*)(Bu2 + (bk + 16) * 72 + bf) = v;
        }
        __syncthreads();
    }

    // epilogue: act = gelu(g) * u -> g_act[pos, f]
#pragma unroll
    for (int m = 0; m < 2; m++) {
        const int rbase = pos_base + wm * 32 + m * 16 + lr;
#pragma unroll
        for (int n = 0; n < 4; n++) {
            const int c = n0 + wn * 32 + n * 8 + 2 * lc;
            if (rbase < seg_end) {
                float a0 = gelu_tanh(accg[m][n][0]) * accu[m][n][0];
                float a1 = gelu_tanh(accg[m][n][1]) * accu[m][n][1];
                *(float2*)(g_act + (size_t)rbase * FDIM + c) = make_float2(a0, a1);
            }
            if (rbase + 8 < seg_end) {
                float a2 = gelu_tanh(accg[m][n][2]) * accu[m][n][2];
                float a3 = gelu_tanh(accg[m][n][3]) * accu[m][n][3];
                *(float2*)(g_act + (size_t)(rbase + 8) * FDIM + c) = make_float2(a2, a3);
            }
        }
    }
}

// ---------------- mlp2: y = w * (act @ Wd), per expert, packed rows ----------------
__global__ void __launch_bounds__(256) k_mlp2(const float* __restrict__ wd) {
    extern __shared__ uint32_t smem[];
    const int e = blockIdx.z;
    const int seg_beg = g_offsets[e];
    const int seg_end = g_offsets[e + 1];
    const int seg_len = seg_end - seg_beg;
    if ((int)blockIdx.y * 128 >= seg_len) return;
    const int pos_base = seg_beg + blockIdx.y * 128;
    const int n0 = blockIdx.x * 64;

    uint32_t* sA = smem;          // 2 * 4608
    uint32_t* sB = smem + 9216;   // 2 * 2304

    const int tid = threadIdx.x;
    const int lane = tid & 31;
    const int warp = tid >> 5;
    const int wm = warp & 3;
    const int wn = warp >> 2;
    const int lr = lane >> 2;
    const int lc = lane & 3;

    const int ar = tid >> 1;
    const int aj = (tid & 1) * 16;
    int apos = pos_base + ar;
    if (apos >= seg_end) apos = seg_end - 1;
    const float* aptr = g_act + (size_t)apos * FDIM + aj;

    const int bk = tid >> 4;
    const int bf = (tid & 15) * 4;
    const float* bp = wd + (size_t)e * FDIM * DDIM + (size_t)bk * DDIM + n0 + bf;

    float acc[2][4][4];
#pragma unroll
    for (int m = 0; m < 2; m++)
#pragma unroll
        for (int n = 0; n < 4; n++)
#pragma unroll
            for (int i = 0; i < 4; i++) acc[m][n][i] = 0.0f;

    float4 ra[4], rb[2];
#pragma unroll
    for (int i = 0; i < 4; i++) ra[i] = *(const float4*)(aptr + i * 4);
    rb[0] = *(const float4*)(bp);
    rb[1] = *(const float4*)(bp + (size_t)16 * DDIM);
    {
        uint32_t* A = sA;
#pragma unroll
        for (int i = 0; i < 4; i++) {
            A[ar * 36 + aj + i * 4 + 0] = f2tf(ra[i].x);
            A[ar * 36 + aj + i * 4 + 1] = f2tf(ra[i].y);
            A[ar * 36 + aj + i * 4 + 2] = f2tf(ra[i].z);
            A[ar * 36 + aj + i * 4 + 3] = f2tf(ra[i].w);
        }
        uint4 v;
        v.x = f2tf(rb[0].x); v.y = f2tf(rb[0].y); v.z = f2tf(rb[0].z); v.w = f2tf(rb[0].w);
        *(uint4*)(sB + bk * 72 + bf) = v;
        v.x = f2tf(rb[1].x); v.y = f2tf(rb[1].y); v.z = f2tf(rb[1].z); v.w = f2tf(rb[1].w);
        *(uint4*)(sB + (bk + 16) * 72 + bf) = v;
    }
    __syncthreads();

    const int KT = FDIM / 32;  // 128
    for (int kt = 0; kt < KT; ++kt) {
        const int buf = kt & 1;
        if (kt + 1 < KT) {
            const int k0 = (kt + 1) * 32;
#pragma unroll
            for (int i = 0; i < 4; i++) ra[i] = *(const float4*)(aptr + k0 + i * 4);
            rb[0] = *(const float4*)(bp + (size_t)k0 * DDIM);
            rb[1] = *(const float4*)(bp + (size_t)(k0 + 16) * DDIM);
        }
        const uint32_t* A = sA + buf * 4608;
        const uint32_t* B = sB + buf * 2304;
#pragma unroll
        for (int ks = 0; ks < 4; ++ks) {
            const int k = ks * 8;
            uint32_t a[2][4];
#pragma unroll
            for (int m = 0; m < 2; m++) {
                const int r0 = wm * 32 + m * 16;
                a[m][0] = A[(r0 + lr) * 36 + k + lc];
                a[m][1] = A[(r0 + 8 + lr) * 36 + k + lc];
                a[m][2] = A[(r0 + lr) * 36 + k + 4 + lc];
                a[m][3] = A[(r0 + 8 + lr) * 36 + k + 4 + lc];
            }
#pragma unroll
            for (int n = 0; n < 4; n++) {
                const int c0 = wn * 32 + n * 8 + lr;
                uint32_t b2[2];
                b2[0] = B[(k + lc) * 72 + c0];
                b2[1] = B[(k + 4 + lc) * 72 + c0];
#pragma unroll
                for (int m = 0; m < 2; m++) mma8(acc[m][n], a[m], b2);
            }
        }
        if (kt + 1 < KT) {
            const int nb = buf ^ 1;
            uint32_t* A2 = sA + nb * 4608;
            uint32_t* B2 = sB + nb * 2304;
#pragma unroll
            for (int i = 0; i < 4; i++) {
                A2[ar * 36 + aj + i * 4 + 0] = f2tf(ra[i].x);
                A2[ar * 36 + aj + i * 4 + 1] = f2tf(ra[i].y);
                A2[ar * 36 + aj + i * 4 + 2] = f2tf(ra[i].z);
                A2[ar * 36 + aj + i * 4 + 3] = f2tf(ra[i].w);
            }
            uint4 v;
            v.x = f2tf(rb[0].x); v.y = f2tf(rb[0].y); v.z = f2tf(rb[0].z); v.w = f2tf(rb[0].w);
            *(uint4*)(B2 + bk * 72 + bf) = v;
            v.x = f2tf(rb[1].x); v.y = f2tf(rb[1].y); v.z = f2tf(rb[1].z); v.w = f2tf(rb[1].w);
            *(uint4*)(B2 + (bk + 16) * 72 + bf) = v;
        }
        __syncthreads();
    }

    // epilogue: scale by routing weight, store to g_y
#pragma unroll
    for (int m = 0; m < 2; m++) {
        const int rbase = pos_base + wm * 32 + m * 16 + lr;
#pragma unroll
        for (int n = 0; n < 4; n++) {
            const int c = n0 + wn * 32 + n * 8 + 2 * lc;
            if (rbase < seg_end) {
                float w = g_row_w[rbase];
                *(float2*)(g_y + (size_t)rbase * DDIM + c) =
                    make_float2(w * acc[m][n][0], w * acc[m][n][1]);
            }
            if (rbase + 8 < seg_end) {
                float w = g_row_w[rbase + 8];
                *(float2*)(g_y + (size_t)(rbase + 8) * DDIM + c) =
                    make_float2(w * acc[m][n][2], w * acc[m][n][3]);
            }
        }
    }
}

// ---------------- combine: out[t] = y[pos(t,0)] + y[pos(t,1)] ----------------
__global__ void k_combine(float* __restrict__ out) {
    const int t = blockIdx.x;
    const int p0 = g_token_pos[t * 2 + 0];
    const int p1 = g_token_pos[t * 2 + 1];
    const float4* y0 = (const float4*)(g_y + (size_t)p0 * DDIM);
    const float4* y1 = (const float4*)(g_y + (size_t)p1 * DDIM);
    float4* o = (float4*)(out + (size_t)t * DDIM);
    for (int i = threadIdx.x; i < DDIM / 4; i += blockDim.x) {
        float4 a = y0[i];
        float4 b = y1[i];
        o[i] = make_float4(a.x + b.x, a.y + b.y, a.z + b.z, a.w + b.w);
    }
}

// ---------------- launch ----------------
extern "C" void kernel_launch(void* const* d_in, const int* in_sizes, int n_in,
                              void* d_out, int out_size) {
    const float* hs = (const float*)d_in[0];  // [T, D]
    const float* gw = (const float*)d_in[1];  // [D, E]
    const float* wg = (const float*)d_in[2];  // [E, D, F]
    const float* wu = (const float*)d_in[3];  // [E, D, F]
    const float* wd = (const float*)d_in[4];  // [E, F, D]
    float* out = (float*)d_out;               // [T, D]

    cudaFuncSetAttribute(k_mlp1, cudaFuncAttributeMaxDynamicSharedMemorySize, 73728);
    cudaFuncSetAttribute(k_mlp2, cudaFuncAttributeMaxDynamicSharedMemorySize, 55296);

    k_reset<<<1, 32>>>();
    k_router<<<TTOK / 8, 256>>>(hs, gw);
    k_scan<<<1, 32>>>();
    k_assign<<<TTOK / 256, 256>>>();
    k_mlp1<<<dim3(FDIM / 64, 16, NEXP), 256, 73728>>>(hs, wg, wu);
    k_mlp2<<<dim3(DDIM / 64, 16, NEXP), 256, 55296>>>(wd);
    k_combine<<<TTOK, 256>>>(out);
}

// round 4
// speedup vs baseline: 2.3947x; 2.3947x over previous
#include <cuda_runtime.h>
#include <cuda_fp16.h>
#include <cstdint>
#include <cstddef>

#define TTOK 2048
#define DDIM 2048
#define FDIM 4096
#define NEXP 8
#define NPOS (TTOK * 2)

#define ASTRIDE 80                         // bytes per A smem row (32 fp16 + pad)
#define BSTRIDE 272                        // bytes per B smem row (128 fp16 + pad)
#define A_BYTES (256 * ASTRIDE)            // 20480
#define STAGE   (A_BYTES + 32 * BSTRIDE)   // 29184
#define DYNSM   (2 * STAGE)                // 58368

// ---------------- scratch ----------------
__device__ int    g_counts[NEXP];
__device__ int    g_offsets[NEXP + 1];
__device__ int    g_fill[NEXP];
__device__ int    g_topk_idx[NPOS];
__device__ float  g_topk_w[NPOS];
__device__ int    g_row_token[NPOS];
__device__ float  g_row_w[NPOS];
__device__ int    g_token_pos[NPOS];
__device__ __half g_act[(size_t)NPOS * FDIM];   // 32 MB fp16
__device__ float  g_y[(size_t)NPOS * DDIM];     // 32 MB

// ---------------- helpers ----------------
__device__ __forceinline__ uint32_t smem_u32(const void* p) {
    uint32_t a;
    asm("{ .reg .u64 t; cvta.to.shared.u64 t, %1; cvt.u32.u64 %0, t; }" : "=r"(a) : "l"(p));
    return a;
}

// pack two fp32 -> f16x2 (lo in low half)
__device__ __forceinline__ uint32_t pack2(float lo, float hi) {
    uint32_t r;
    asm("cvt.rn.f16x2.f32 %0, %1, %2;" : "=r"(r) : "f"(hi), "f"(lo));
    return r;
}

__device__ __forceinline__ void ldsm4(uint32_t* r, uint32_t a) {
    asm volatile("ldmatrix.sync.aligned.m8n8.x4.shared.b16 {%0,%1,%2,%3}, [%4];"
                 : "=r"(r[0]), "=r"(r[1]), "=r"(r[2]), "=r"(r[3]) : "r"(a));
}
__device__ __forceinline__ void ldsm4t(uint32_t* r, uint32_t a) {
    asm volatile("ldmatrix.sync.aligned.m8n8.x4.trans.shared.b16 {%0,%1,%2,%3}, [%4];"
                 : "=r"(r[0]), "=r"(r[1]), "=r"(r[2]), "=r"(r[3]) : "r"(a));
}
__device__ __forceinline__ void mma16(float* c, const uint32_t* a, const uint32_t* b) {
    asm volatile(
        "mma.sync.aligned.m16n8k16.row.col.f32.f16.f16.f32 "
        "{%0,%1,%2,%3},{%4,%5,%6,%7},{%8,%9},{%0,%1,%2,%3};"
        : "+f"(c[0]), "+f"(c[1]), "+f"(c[2]), "+f"(c[3])
        : "r"(a[0]), "r"(a[1]), "r"(a[2]), "r"(a[3]), "r"(b[0]), "r"(b[1]));
}
#define STS64(a, v0, v1) \
    asm volatile("st.shared.v2.b32 [%0], {%1,%2};" :: "r"(a), "r"(v0), "r"(v1))
#define STS128(a, v0, v1, v2, v3) \
    asm volatile("st.shared.v4.b32 [%0], {%1,%2,%3,%4};" :: "r"(a), "r"(v0), "r"(v1), "r"(v2), "r"(v3))

__device__ __forceinline__ float gelu_tanh(float x) {
    float x3 = x * x * x;
    return 0.5f * x * (1.0f + tanhf(0.7978845608028654f * (x + 0.044715f * x3)));
}

// ---------------- router (known-correct from R1) ----------------
__global__ void k_reset() {
    if (threadIdx.x < NEXP) g_counts[threadIdx.x] = 0;
}

__global__ void k_router(const float* __restrict__ hs, const float* __restrict__ gw) {
    const int warp = threadIdx.x >> 5;
    const int lane = threadIdx.x & 31;
    const int t = blockIdx.x * 8 + warp;
    if (t >= TTOK) return;
    float acc[NEXP];
#pragma unroll
    for (int e = 0; e < NEXP; e++) acc[e] = 0.0f;
    const float* hrow = hs + (size_t)t * DDIM;
    for (int d = lane; d < DDIM; d += 32) {
        float x = hrow[d];
        const float* g = gw + d * NEXP;
#pragma unroll
        for (int e = 0; e < NEXP; e++) acc[e] = fmaf(x, g[e], acc[e]);
    }
#pragma unroll
    for (int e = 0; e < NEXP; e++) {
#pragma unroll
        for (int o = 16; o > 0; o >>= 1) acc[e] += __shfl_xor_sync(0xffffffffu, acc[e], o);
    }
    if (lane == 0) {
        float l[NEXP];
#pragma unroll
        for (int e = 0; e < NEXP; e++) l[e] = tanhf(acc[e] / 30.0f) * 30.0f;
        int i0 = 0;
#pragma unroll
        for (int e = 1; e < NEXP; e++) if (l[e] > l[i0]) i0 = e;
        int i1 = -1;
#pragma unroll
        for (int e = 0; e < NEXP; e++) {
            if (e == i0) continue;
            if (i1 < 0 || l[e] > l[i1]) i1 = e;
        }
        float ee = expf(l[i1] - l[i0]);
        g_topk_idx[t * 2 + 0] = i0;
        g_topk_idx[t * 2 + 1] = i1;
        g_topk_w[t * 2 + 0] = 1.0f / (1.0f + ee);
        g_topk_w[t * 2 + 1] = ee / (1.0f + ee);
        atomicAdd(&g_counts[i0], 1);
        atomicAdd(&g_counts[i1], 1);
    }
}

__global__ void k_scan() {
    if (threadIdx.x == 0) {
        int o = 0;
#pragma unroll
        for (int e = 0; e < NEXP; e++) { g_offsets[e] = o; g_fill[e] = o; o += g_counts[e]; }
        g_offsets[NEXP] = o;
    }
}

__global__ void k_assign() {
    const int t = blockIdx.x * blockDim.x + threadIdx.x;
    if (t >= TTOK) return;
#pragma unroll
    for (int k = 0; k < 2; k++) {
        int e = g_topk_idx[t * 2 + k];
        int pos = atomicAdd(&g_fill[e], 1);
        g_row_token[pos] = t;
        g_row_w[pos] = g_topk_w[t * 2 + k];
        g_token_pos[t * 2 + k] = pos;
    }
}

// ============ mlp1: act = gelu(X@Wg) * (X@Wu)  (fp16 mma, M=256, f-block=64) ============
// 512 threads = 16 warps (4m x 4n), warptile 64x32. B cols: 16-blocks = [gate f8 | up f8].
__global__ void __launch_bounds__(512) k_mlp1(const float* __restrict__ hs,
                                              const float* __restrict__ wg,
                                              const float* __restrict__ wu) {
    extern __shared__ uint8_t dsm[];
    const int e = blockIdx.z;
    const int seg_beg = g_offsets[e];
    const int seg_end = g_offsets[e + 1];
    if ((int)blockIdx.y * 256 >= seg_end - seg_beg) return;
    const int pos_base = seg_beg + blockIdx.y * 256;
    const int f0 = blockIdx.x * 64;

    const uint32_t sbase = smem_u32(dsm);
    const int tid = threadIdx.x;
    const int lane = tid & 31;
    const int w = tid >> 5, wm = w & 3, wn = w >> 2;

    // ---- producer coords ----
    const int ar = tid >> 3;          // 0..63 (A row group)
    const int ac = (tid & 7) * 4;     // fp32 col within 32
    const float* arow[4];
#pragma unroll
    for (int p = 0; p < 4; p++) {
        int pos = pos_base + ar + 64 * p;
        if (pos >= seg_end) pos = seg_end - 1;
        arow[p] = hs + (size_t)g_row_token[pos] * DDIM + ac;
    }
    const int h = tid >> 8;           // 0=gate, 1=up
    const int uu = tid & 255;
    const int bk = uu >> 4;           // k row 0..15 (+16 for pass 1)
    const int bf = (uu & 15) * 4;     // f col 0..60
    const float* bsrc = (h ? wu : wg) + (size_t)e * DDIM * FDIM + f0 + bf;
    const int bn = 16 * (bf >> 3) + (bf & 7) + 8 * h;  // interleaved smem n col

    float4 ra[4], rb[2];
#pragma unroll
    for (int p = 0; p < 4; p++) ra[p] = *(const float4*)(arow[p]);
#pragma unroll
    for (int p = 0; p < 2; p++) rb[p] = *(const float4*)(bsrc + (size_t)(bk + 16 * p) * FDIM);

    float acc[4][4][4];
#pragma unroll
    for (int a = 0; a < 4; a++)
#pragma unroll
        for (int b = 0; b < 4; b++)
#pragma unroll
            for (int i = 0; i < 4; i++) acc[a][b][i] = 0.0f;

    const int KT = DDIM / 32;  // 64
    for (int c = 0; c < KT; c++) {
        const uint32_t st = sbase + (uint32_t)(c & 1) * STAGE;
        // STS A (fp32->fp16)
#pragma unroll
        for (int p = 0; p < 4; p++) {
            uint32_t a = st + (uint32_t)(ar + 64 * p) * ASTRIDE + (tid & 7) * 8;
            STS64(a, pack2(ra[p].x, ra[p].y), pack2(ra[p].z, ra[p].w));
        }
        // STS B (K-major, gate/up interleaved by 8)
#pragma unroll
        for (int p = 0; p < 2; p++) {
            uint32_t a = st + A_BYTES + (uint32_t)(bk + 16 * p) * BSTRIDE + bn * 2;
            STS64(a, pack2(rb[p].x, rb[p].y), pack2(rb[p].z, rb[p].w));
        }
        __syncthreads();
        if (c + 1 < KT) {
            const int k0 = (c + 1) * 32;
#pragma unroll
            for (int p = 0; p < 4; p++) ra[p] = *(const float4*)(arow[p] + k0);
#pragma unroll
            for (int p = 0; p < 2; p++) rb[p] = *(const float4*)(bsrc + (size_t)(k0 + bk + 16 * p) * FDIM);
        }
        // compute
        const uint32_t sA = st;
        const uint32_t sB = st + A_BYTES;
        const int grp = lane >> 3;
#pragma unroll
        for (int ks = 0; ks < 2; ks++) {
            uint32_t bfr[4][2];
#pragma unroll
            for (int hn = 0; hn < 2; hn++) {
                uint32_t r[4];
                uint32_t addr = sB + (uint32_t)(ks * 16 + (grp & 1) * 8 + (lane & 7)) * BSTRIDE +
                                (uint32_t)(wn * 32 + hn * 16 + (grp >> 1) * 8) * 2;
                ldsm4t(r, addr);
                bfr[hn * 2 + 0][0] = r[0]; bfr[hn * 2 + 0][1] = r[1];
                bfr[hn * 2 + 1][0] = r[2]; bfr[hn * 2 + 1][1] = r[3];
            }
#pragma unroll
            for (int mt = 0; mt < 4; mt++) {
                uint32_t afr[4];
                uint32_t addr = sA + (uint32_t)(wm * 64 + mt * 16 + (grp & 1) * 8 + (lane & 7)) * ASTRIDE +
                                (uint32_t)(ks * 16 + (grp >> 1) * 8) * 2;
                ldsm4(afr, addr);
#pragma unroll
                for (int nt = 0; nt < 4; nt++) mma16(acc[mt][nt], afr, bfr[nt]);
            }
        }
        __syncthreads();
    }

    // epilogue: gate/up adjacent in n-blocks -> pair within thread fragments
    const int l4 = lane >> 2, l2 = lane & 3;
#pragma unroll
    for (int mt = 0; mt < 4; mt++) {
        const int r0 = pos_base + wm * 64 + mt * 16 + l4;
#pragma unroll
        for (int ntp = 0; ntp < 2; ntp++) {
            const int fc = f0 + wn * 16 + ntp * 8 + 2 * l2;
            const float* g = acc[mt][2 * ntp];
            const float* u = acc[mt][2 * ntp + 1];
            if (r0 < seg_end) {
                uint32_t v = pack2(gelu_tanh(g[0]) * u[0], gelu_tanh(g[1]) * u[1]);
                *(uint32_t*)(&g_act[(size_t)r0 * FDIM + fc]) = v;
            }
            if (r0 + 8 < seg_end) {
                uint32_t v = pack2(gelu_tanh(g[2]) * u[2], gelu_tanh(g[3]) * u[3]);
                *(uint32_t*)(&g_act[(size_t)(r0 + 8) * FDIM + fc]) = v;
            }
        }
    }
}

// ============ mlp2: y = w * (act @ Wd)  (fp16 mma, M=256, N=128) ============
__global__ void __launch_bounds__(512) k_mlp2(const float* __restrict__ wd) {
    extern __shared__ uint8_t dsm[];
    const int e = blockIdx.z;
    const int seg_beg = g_offsets[e];
    const int seg_end = g_offsets[e + 1];
    if ((int)blockIdx.y * 256 >= seg_end - seg_beg) return;
    const int pos_base = seg_beg + blockIdx.y * 256;
    const int n0 = blockIdx.x * 128;

    const uint32_t sbase = smem_u32(dsm);
    const int tid = threadIdx.x;
    const int lane = tid & 31;
    const int w = tid >> 5, wm = w & 3, wn = w >> 2;

    // A producer: fp16 passthrough, 128 rows/pass, 2 passes
    const int ar = tid >> 2;          // 0..127
    const int ac = (tid & 3) * 8;     // fp16 col within 32
    const __half* arow[2];
#pragma unroll
    for (int p = 0; p < 2; p++) {
        int pos = pos_base + ar + 128 * p;
        if (pos >= seg_end) pos = seg_end - 1;
        arow[p] = g_act + (size_t)pos * FDIM + ac;
    }
    // B producer: 16 k-rows/pass, 2 passes, 32 lanes x float4 across n=128
    const int bk = tid >> 5;          // 0..15
    const int bf = (tid & 31) * 4;    // n col 0..124
    const float* bsrc = wd + (size_t)e * FDIM * DDIM + n0 + bf;

    uint4 ra[2];
    float4 rb[2];
#pragma unroll
    for (int p = 0; p < 2; p++) ra[p] = *(const uint4*)(arow[p]);
#pragma unroll
    for (int p = 0; p < 2; p++) rb[p] = *(const float4*)(bsrc + (size_t)(bk + 16 * p) * DDIM);

    float acc[4][4][4];
#pragma unroll
    for (int a = 0; a < 4; a++)
#pragma unroll
        for (int b = 0; b < 4; b++)
#pragma unroll
            for (int i = 0; i < 4; i++) acc[a][b][i] = 0.0f;

    const int KT = FDIM / 32;  // 128
    for (int c = 0; c < KT; c++) {
        const uint32_t st = sbase + (uint32_t)(c & 1) * STAGE;
#pragma unroll
        for (int p = 0; p < 2; p++) {
            uint32_t a = st + (uint32_t)(ar + 128 * p) * ASTRIDE + (tid & 3) * 16;
            STS128(a, ra[p].x, ra[p].y, ra[p].z, ra[p].w);
        }
#pragma unroll
        for (int p = 0; p < 2; p++) {
            uint32_t a = st + A_BYTES + (uint32_t)(bk + 16 * p) * BSTRIDE + bf * 2;
            STS64(a, pack2(rb[p].x, rb[p].y), pack2(rb[p].z, rb[p].w));
        }
        __syncthreads();
        if (c + 1 < KT) {
            const int k0 = (c + 1) * 32;
#pragma unroll
            for (int p = 0; p < 2; p++) ra[p] = *(const uint4*)(arow[p] + k0);
#pragma unroll
            for (int p = 0; p < 2; p++) rb[p] = *(const float4*)(bsrc + (size_t)(k0 + bk + 16 * p) * DDIM);
        }
        const uint32_t sA = st;
        const uint32_t sB = st + A_BYTES;
        const int grp = lane >> 3;
#pragma unroll
        for (int ks = 0; ks < 2; ks++) {
            uint32_t bfr[4][2];
#pragma unroll
            for (int hn = 0; hn < 2; hn++) {
                uint32_t r[4];
                uint32_t addr = sB + (uint32_t)(ks * 16 + (grp & 1) * 8 + (lane & 7)) * BSTRIDE +
                                (uint32_t)(wn * 32 + hn * 16 + (grp >> 1) * 8) * 2;
                ldsm4t(r, addr);
                bfr[hn * 2 + 0][0] = r[0]; bfr[hn * 2 + 0][1] = r[1];
                bfr[hn * 2 + 1][0] = r[2]; bfr[hn * 2 + 1][1] = r[3];
            }
#pragma unroll
            for (int mt = 0; mt < 4; mt++) {
                uint32_t afr[4];
                uint32_t addr = sA + (uint32_t)(wm * 64 + mt * 16 + (grp & 1) * 8 + (lane & 7)) * ASTRIDE +
                                (uint32_t)(ks * 16 + (grp >> 1) * 8) * 2;
                ldsm4(afr, addr);
#pragma unroll
                for (int nt = 0; nt < 4; nt++) mma16(acc[mt][nt], afr, bfr[nt]);
            }
        }
        __syncthreads();
    }

    // epilogue: scale by routing weight -> g_y (fp32)
    const int l4 = lane >> 2, l2 = lane & 3;
#pragma unroll
    for (int mt = 0; mt < 4; mt++) {
        const int r0 = pos_base + wm * 64 + mt * 16 + l4;
        const int r1 = r0 + 8;
        const float w0 = (r0 < seg_end) ? g_row_w[r0] : 0.0f;
        const float w1 = (r1 < seg_end) ? g_row_w[r1] : 0.0f;
#pragma unroll
        for (int nt = 0; nt < 4; nt++) {
            const int n = n0 + wn * 32 + nt * 8 + 2 * l2;
            if (r0 < seg_end)
                *(float2*)(&g_y[(size_t)r0 * DDIM + n]) =
                    make_float2(w0 * acc[mt][nt][0], w0 * acc[mt][nt][1]);
            if (r1 < seg_end)
                *(float2*)(&g_y[(size_t)r1 * DDIM + n]) =
                    make_float2(w1 * acc[mt][nt][2], w1 * acc[mt][nt][3]);
        }
    }
}

// ---------------- combine ----------------
__global__ void k_combine(float* __restrict__ out) {
    const int t = blockIdx.x;
    const int p0 = g_token_pos[t * 2 + 0];
    const int p1 = g_token_pos[t * 2 + 1];
    const float4* y0 = (const float4*)(g_y + (size_t)p0 * DDIM);
    const float4* y1 = (const float4*)(g_y + (size_t)p1 * DDIM);
    float4* o = (float4*)(out + (size_t)t * DDIM);
    for (int i = threadIdx.x; i < DDIM / 4; i += blockDim.x) {
        float4 a = y0[i];
        float4 b = y1[i];
        o[i] = make_float4(a.x + b.x, a.y + b.y, a.z + b.z, a.w + b.w);
    }
}

// ---------------- launch ----------------
extern "C" void kernel_launch(void* const* d_in, const int* in_sizes, int n_in,
                              void* d_out, int out_size) {
    (void)in_sizes; (void)n_in; (void)out_size;
    const float* hs = (const float*)d_in[0];
    const float* gw = (const float*)d_in[1];
    const float* wg = (const float*)d_in[2];
    const float* wu = (const float*)d_in[3];
    const float* wd = (const float*)d_in[4];
    float* out = (float*)d_out;

    cudaFuncSetAttribute(k_mlp1, cudaFuncAttributeMaxDynamicSharedMemorySize, DYNSM);
    cudaFuncSetAttribute(k_mlp2, cudaFuncAttributeMaxDynamicSharedMemorySize, DYNSM);

    k_reset<<<1, 32>>>();
    k_router<<<TTOK / 8, 256>>>(hs, gw);
    k_scan<<<1, 32>>>();
    k_assign<<<TTOK / 256, 256>>>();
    k_mlp1<<<dim3(FDIM / 64, NPOS / 256, NEXP), 512, DYNSM>>>(hs, wg, wu);
    k_mlp2<<<dim3(DDIM / 128, NPOS / 256, NEXP), 512, DYNSM>>>(wd);
    k_combine<<<TTOK, 256>>>(out);
}